// round 6
// baseline (speedup 1.0000x reference)
#include <cuda_runtime.h>

// ThermoQuantizer — GB300 (sm_103a)
//
// Per group of 128 contiguous floats:
//   m  = max(mean(|x|), 1e-5);  u = x/m
//   qx = m * sum_k softmax_k(-(u-c_k)^2/T) * c_k,  c_k = -1 + k*(2/15), T = 0.500001
//   out = x + 0.7*(qx - x)
//
// Uniform codebook => softmax weights geometric in k:
//   w_k ∝ exp((2u c_k - c_k^2)/T). Anchor at k=15 for u>=0 (j = 15-k):
//   w_j = e^j D_j,  e = exp(-2Δ|u|/T) ∈ (0,1],  D_j = exp(-(1-jΔ)^2/T) (symmetric).
//   qx_norm(|u|) = P_num(e)/P_den(e) — two degree-15 constant-coeff polys;
//   numerator coeffs D_j(1-jΔ) are antisymmetric => sign-fold for u<0 is exact.
// Per element: 1 EX2 + 1 RCP-class div + 30 FFMA-imm. den >= 0.135 always.

#define FULLMASK 0xFFFFFFFFu

__device__ __forceinline__ float ex2f(float x) {
    float y;
    asm("ex2.approx.ftz.f32 %0, %1;" : "=f"(y) : "f"(x));
    return y;
}

__device__ __forceinline__ float fdiv_fast(float a, float b) {
    float y;
    asm("div.approx.f32 %0, %1, %2;" : "=f"(y) : "f"(a), "f"(b));
    return y;
}

// qx_norm(|u|) via rational poly in e = 2^(-K*|u|),
// K = (4/15)/(0.500001) * log2(e) = 0.76943434
__device__ __forceinline__ float soft_q(float au) {
    const float e = ex2f(-0.76943434f * au);

    // Denominator: sum_j e^j * D_j, D_j = exp(-(1-j*2/15)^2/T), symmetric.
    float d = 0.13533582f;                 // j=15
    d = fmaf(d, e, 0.22263490f);           // j=14
    d = fmaf(d, e, 0.34110996f);           // j=13
    d = fmaf(d, e, 0.48675225f);           // j=12
    d = fmaf(d, e, 0.64690530f);           // j=11
    d = fmaf(d, e, 0.80073740f);           // j=10
    d = fmaf(d, e, 0.92311630f);           // j=9
    d = fmaf(d, e, 0.99114990f);           // j=8
    d = fmaf(d, e, 0.99114990f);           // j=7
    d = fmaf(d, e, 0.92311630f);           // j=6
    d = fmaf(d, e, 0.80073740f);           // j=5
    d = fmaf(d, e, 0.64690530f);           // j=4
    d = fmaf(d, e, 0.48675225f);           // j=3
    d = fmaf(d, e, 0.34110996f);           // j=2
    d = fmaf(d, e, 0.22263490f);           // j=1
    d = fmaf(d, e, 0.13533582f);           // j=0

    // Numerator: sum_j e^j * D_j * (1 - j*2/15)  (antisymmetric).
    float n = -0.13533582f;                // j=15
    n = fmaf(n, e, -0.19295025f);          // j=14
    n = fmaf(n, e, -0.25014730f);          // j=13
    n = fmaf(n, e, -0.29205135f);          // j=12
    n = fmaf(n, e, -0.30188915f);          // j=11
    n = fmaf(n, e, -0.26691247f);          // j=10
    n = fmaf(n, e, -0.18462326f);          // j=9
    n = fmaf(n, e, -0.06607666f);          // j=8
    n = fmaf(n, e,  0.06607666f);          // j=7
    n = fmaf(n, e,  0.18462326f);          // j=6
    n = fmaf(n, e,  0.26691247f);          // j=5
    n = fmaf(n, e,  0.30188915f);          // j=4
    n = fmaf(n, e,  0.29205135f);          // j=3
    n = fmaf(n, e,  0.25014730f);          // j=2
    n = fmaf(n, e,  0.19295025f);          // j=1
    n = fmaf(n, e,  0.13533582f);          // j=0

    return fdiv_fast(n, d);                // in [0, 1)
}

__global__ void __launch_bounds__(256)
ThermoQuantizer_50122268345057_kernel(const float4* __restrict__ x4,
                                      float4* __restrict__ o4,
                                      int ngroups) {
    const int gwarp = (blockIdx.x * blockDim.x + threadIdx.x) >> 5;
    const int lane  = threadIdx.x & 31;
    if (gwarp >= ngroups) return;

    // One warp = one group of 128 floats; lane owns one float4
    // (512 B coalesced per warp). Streaming loads: single-pass, no reuse.
    const int idx = gwarp * 32 + lane;
    const float4 xv = __ldcs(&x4[idx]);

    const float a0 = fabsf(xv.x);
    const float a1 = fabsf(xv.y);
    const float a2 = fabsf(xv.z);
    const float a3 = fabsf(xv.w);

    // Group mean(|x|) via warp butterfly reduction (5 shuffles).
    float s = (a0 + a1) + (a2 + a3);
    #pragma unroll
    for (int o = 16; o; o >>= 1)
        s += __shfl_xor_sync(FULLMASK, s, o);

    const float m  = fmaxf(s * (1.0f / 128.0f), 1e-5f);  // clip(mean|x|, 1e-5)
    const float rs = 1.0f / m;

    // 8 independent Horner chains (4 elems x num/den) cover FFMA latency.
    const float q0 = soft_q(a0 * rs);
    const float q1 = soft_q(a1 * rs);
    const float q2 = soft_q(a2 * rs);
    const float q3 = soft_q(a3 * rs);

    const float qx0 = copysignf(q0 * m, xv.x);
    const float qx1 = copysignf(q1 * m, xv.y);
    const float qx2 = copysignf(q2 * m, xv.z);
    const float qx3 = copysignf(q3 * m, xv.w);

    // out = x + 0.7*(qx - x)
    float4 ov;
    ov.x = fmaf(0.7f, qx0 - xv.x, xv.x);
    ov.y = fmaf(0.7f, qx1 - xv.y, xv.y);
    ov.z = fmaf(0.7f, qx2 - xv.z, xv.z);
    ov.w = fmaf(0.7f, qx3 - xv.w, xv.w);
    __stcs(&o4[idx], ov);                  // streaming store
}

extern "C" void kernel_launch(void* const* d_in, const int* in_sizes, int n_in,
                              void* d_out, int out_size) {
    const float* x = (const float*)d_in[0];
    float* out = (float*)d_out;
    const int n = in_sizes[0];
    const int ngroups = n / 128;                 // 131072 for 4096x4096
    const int warps_per_block = 256 / 32;        // 8
    const int blocks = (ngroups + warps_per_block - 1) / warps_per_block;
    ThermoQuantizer_50122268345057_kernel<<<blocks, 256>>>(
        (const float4*)x, (float4*)out, ngroups);
}

// round 7
// speedup vs baseline: 1.1491x; 1.1491x over previous
#include <cuda_runtime.h>

// ThermoQuantizer — GB300 (sm_103a), round 7: shared-memory LUT version.
//
// R6 measured: 33.5us, issue=81.5%, fma=57.2%, dram=34.8% -> ISSUE-BOUND on the
// 30-FFMA/element rational poly. Replace per-element poly with a piecewise-
// linear LUT of qx_norm(|u|): 2048 segments over [0,16], entry i = (A,B) with
// qx_norm(t/128) ~= B*t + A for t in [i, i+1)  (t = |u|*128, index units).
// Interp error ~ f''*h^2/8 ~ 8e-6  (tolerance 1e-3; R6 exact math gave 5e-7).
// Per element: |x|, mul, clamp, F2I, LDS.64, FFMA, mul, copysign, FFMA ~ 10
// issues vs ~38 before. Persistent grid (148*4 blocks) amortizes LUT build to
// ~7% of the old math and keeps HBM the only binder (~20us floor).

#define FULLMASK 0xFFFFFFFFu
#define LUT_N 2048
#define INV_H 128.0f                 // LUT entries per unit |u| (h = 1/128)
#define THREADS 256
#define NBLOCKS 592                  // 148 SMs * 4 blocks (32 warps/SM)
#define WARPS_PER_BLOCK (THREADS / 32)
#define TOTAL_WARPS (NBLOCKS * WARPS_PER_BLOCK)   // 4736

__device__ __forceinline__ float ex2f(float x) {
    float y;
    asm("ex2.approx.ftz.f32 %0, %1;" : "=f"(y) : "f"(x));
    return y;
}

__device__ __forceinline__ float fdiv_fast(float a, float b) {
    float y;
    asm("div.approx.f32 %0, %1, %2;" : "=f"(y) : "f"(a), "f"(b));
    return y;
}

// Exact closed form (hand-verified in R1-R6, rel_err 5e-7 measured):
// qx_norm(|u|) = P_num(e)/P_den(e), e = 2^(-0.76943434*|u|).
// Used only to BUILD the LUT (2049 evals per block).
__device__ __forceinline__ float soft_q(float au) {
    const float e = ex2f(-0.76943434f * au);

    float d = 0.13533582f;
    d = fmaf(d, e, 0.22263490f);
    d = fmaf(d, e, 0.34110996f);
    d = fmaf(d, e, 0.48675225f);
    d = fmaf(d, e, 0.64690530f);
    d = fmaf(d, e, 0.80073740f);
    d = fmaf(d, e, 0.92311630f);
    d = fmaf(d, e, 0.99114990f);
    d = fmaf(d, e, 0.99114990f);
    d = fmaf(d, e, 0.92311630f);
    d = fmaf(d, e, 0.80073740f);
    d = fmaf(d, e, 0.64690530f);
    d = fmaf(d, e, 0.48675225f);
    d = fmaf(d, e, 0.34110996f);
    d = fmaf(d, e, 0.22263490f);
    d = fmaf(d, e, 0.13533582f);

    float n = -0.13533582f;
    n = fmaf(n, e, -0.19295025f);
    n = fmaf(n, e, -0.25014730f);
    n = fmaf(n, e, -0.29205135f);
    n = fmaf(n, e, -0.30188915f);
    n = fmaf(n, e, -0.26691247f);
    n = fmaf(n, e, -0.18462326f);
    n = fmaf(n, e, -0.06607666f);
    n = fmaf(n, e,  0.06607666f);
    n = fmaf(n, e,  0.18462326f);
    n = fmaf(n, e,  0.26691247f);
    n = fmaf(n, e,  0.30188915f);
    n = fmaf(n, e,  0.29205135f);
    n = fmaf(n, e,  0.25014730f);
    n = fmaf(n, e,  0.19295025f);
    n = fmaf(n, e,  0.13533582f);

    return fdiv_fast(n, d);
}

__global__ void __launch_bounds__(THREADS, 4)
ThermoQuantizer_50122268345057_kernel(const float4* __restrict__ x4,
                                      float4* __restrict__ o4,
                                      int ngroups) {
    __shared__ float2 lut[LUT_N];     // (A, B): qx_norm ~= fma(B, t, A), t in index units
    __shared__ float  f_last;         // f(LUT_N * h)

    const int tid = threadIdx.x;

    // ---- Phase 1: sample f at 2049 knots (store f_i in lut[i].x) ----
    #pragma unroll
    for (int k = 0; k < LUT_N / THREADS; k++) {
        const int i = tid + k * THREADS;
        lut[i].x = soft_q((float)i * (1.0f / INV_H));
    }
    if (tid == 0) f_last = soft_q((float)LUT_N * (1.0f / INV_H));
    __syncthreads();

    // ---- Phase 2: read neighbor pairs, then rewrite entries as (A, B) ----
    float fi[LUT_N / THREADS], fip[LUT_N / THREADS];
    #pragma unroll
    for (int k = 0; k < LUT_N / THREADS; k++) {
        const int i = tid + k * THREADS;
        fi[k]  = lut[i].x;
        fip[k] = (i + 1 < LUT_N) ? lut[i + 1].x : f_last;
    }
    __syncthreads();
    #pragma unroll
    for (int k = 0; k < LUT_N / THREADS; k++) {
        const int i = tid + k * THREADS;
        const float df = fip[k] - fi[k];
        // qx = f_i + (t - i)*df = fma(df, t, f_i - i*df)
        lut[i] = make_float2(fmaf(-(float)i, df, fi[k]), df);
    }
    __syncthreads();

    // ---- Phase 3: grid-stride over groups; one warp = one group of 128 ----
    const int wid  = tid >> 5;
    const int lane = tid & 31;
    int g = blockIdx.x * WARPS_PER_BLOCK + wid;
    if (g >= ngroups) return;

    float4 xv = __ldcs(&x4[g * 32 + lane]);      // prefetch first tile

    for (; g < ngroups; g += TOTAL_WARPS) {
        // Prefetch next tile to keep >=2 LDGs in flight per warp.
        const int gn = g + TOTAL_WARPS;
        float4 xn = xv;
        if (gn < ngroups) xn = __ldcs(&x4[gn * 32 + lane]);

        const float a0 = fabsf(xv.x);
        const float a1 = fabsf(xv.y);
        const float a2 = fabsf(xv.z);
        const float a3 = fabsf(xv.w);

        // Group mean(|x|) via warp butterfly (5 shuffles).
        float s = (a0 + a1) + (a2 + a3);
        #pragma unroll
        for (int o = 16; o; o >>= 1)
            s += __shfl_xor_sync(FULLMASK, s, o);

        const float m    = fmaxf(s * (1.0f / 128.0f), 1e-5f);  // clip(mean|x|,1e-5)
        const float sc   = fdiv_fast(INV_H, m);                // t = |x| * 128/m
        const float w07m = 0.7f * m;                           // folds 0.7*qx scaling

        const float t0 = fminf(a0 * sc, 2047.99f);
        const float t1 = fminf(a1 * sc, 2047.99f);
        const float t2 = fminf(a2 * sc, 2047.99f);
        const float t3 = fminf(a3 * sc, 2047.99f);

        const float2 e0 = lut[(int)t0];
        const float2 e1 = lut[(int)t1];
        const float2 e2 = lut[(int)t2];
        const float2 e3 = lut[(int)t3];

        const float q0 = fmaf(e0.y, t0, e0.x);   // qx_norm(|u|)
        const float q1 = fmaf(e1.y, t1, e1.x);
        const float q2 = fmaf(e2.y, t2, e2.x);
        const float q3 = fmaf(e3.y, t3, e3.x);

        // out = 0.3*x + 0.7*qx,  qx = copysign(q * m, x)
        float4 ov;
        ov.x = fmaf(0.3f, xv.x, copysignf(q0 * w07m, xv.x));
        ov.y = fmaf(0.3f, xv.y, copysignf(q1 * w07m, xv.y));
        ov.z = fmaf(0.3f, xv.z, copysignf(q2 * w07m, xv.z));
        ov.w = fmaf(0.3f, xv.w, copysignf(q3 * w07m, xv.w));
        __stcs(&o4[g * 32 + lane], ov);

        xv = xn;
    }
}

extern "C" void kernel_launch(void* const* d_in, const int* in_sizes, int n_in,
                              void* d_out, int out_size) {
    const float* x = (const float*)d_in[0];
    float* out = (float*)d_out;
    const int n = in_sizes[0];
    const int ngroups = n / 128;                 // 131072 for 4096x4096
    ThermoQuantizer_50122268345057_kernel<<<NBLOCKS, THREADS>>>(
        (const float4*)x, (float4*)out, ngroups);
}